// round 5
// baseline (speedup 1.0000x reference)
#include <cuda_runtime.h>
#include <cuda_bf16.h>

// Fixed problem shapes (ContConv1d_29583734735380)
#define BSZ   2
#define LSEQ  2048
#define CIN   32
#define COUT  32
#define HID   128
#define NPOS  (BSZ * LSEQ)
#define NCO   (CIN * COUT)     // 1024
#define NPREP 8                // V-builder blocks (NCO / HID)
#define NWORK 512              // worker blocks, 8 warps each -> 4096 positions
#define NBLK  (NPREP + NWORK)
#define SPIN_MAX (1u << 22)    // bounded tight poll; then self-compute fallback

// Scratch (no device allocation allowed — __device__ globals; zero-init)
__device__ float    g_V[NCO];   // collapsed kernel matrix V[c*COUT+o]
__device__ int      g_fast;     // 1 iff all biases are exactly zero
__device__ unsigned g_done;     // prep blocks finished (reset each launch)
__device__ unsigned g_wdone;    // worker blocks finished (reset each launch)

__device__ __forceinline__ int read_K(const int* __restrict__ Kp) {
    int k = Kp ? __ldg(Kp) : 16;
    if (k < 1 || k > LSEQ) k = 16;   // guard odd metadata dtype
    return k;
}

__device__ __forceinline__ unsigned ld_volatile_u32(const unsigned* p) {
    unsigned v;
    asm volatile("ld.volatile.global.u32 %0, [%1];" : "=r"(v) : "l"(p));
    return v;
}

// Bias L1 partial over 256 threads; returns block-total on thread 0 via smem.
__device__ __forceinline__ float bias_l1(const float* __restrict__ b1,
                                         const float* __restrict__ b2,
                                         const float* __restrict__ b3,
                                         int t, float* red8 /* >=8 floats */) {
    float s = 0.0f;
    for (int idx = t; idx < 2 * HID + NCO; idx += 256) {
        float x = (idx < HID)     ? b1[idx]
                : (idx < 2 * HID) ? b2[idx - HID]
                :                   b3[idx - 2 * HID];
        s += fabsf(x);
    }
#pragma unroll
    for (int o = 16; o > 0; o >>= 1) s += __shfl_down_sync(0xffffffffu, s, o);
    if ((t & 31) == 0) red8[t >> 5] = s;
    __syncthreads();
    float tot = 0.0f;
#pragma unroll
    for (int w = 0; w < 8; w++) tot += red8[w];
    return tot;
}

// ---------------------------------------------------------------------------
// ONE kernel. blocks [0,8): build V = relu(relu(W1)@W2)@W3 + bias check.
// blocks [8,520): one warp per position; overlap S/feature work with prep,
// bounded tight-poll on g_done (self-compute fallback on timeout), then
// out = S * (f @ V). Exact nonzero-bias fallback inlined (dead for ref).
// ---------------------------------------------------------------------------
__global__ void __launch_bounds__(256, 4) fused_kernel(
        const float* __restrict__ times,
        const float* __restrict__ feat,
        const float* __restrict__ W1,
        const float* __restrict__ b1,
        const float* __restrict__ W2,
        const float* __restrict__ b2,
        const float* __restrict__ W3,
        const float* __restrict__ b3,
        const int*   __restrict__ Kp,
        float*       __restrict__ out) {
    const int t   = threadIdx.x;   // 0..255
    const int bid = blockIdx.x;

    if (bid < NPREP) {
        // ===================== prep =====================
        __shared__ float r[HID];
        __shared__ float part[2 * HID];
        __shared__ float v[HID];
        __shared__ float red[8];
        const int col  = t & (HID - 1);
        const int half = t >> 7;

        if (t < HID) r[t] = fmaxf(W1[t], 0.0f);

        if (bid == 0) {
            float tot = bias_l1(b1, b2, b3, t, red);
            if (t == 0) g_fast = (tot == 0.0f) ? 1 : 0;
        } else {
            __syncthreads();  // match bias_l1's internal barrier
        }
        __syncthreads();

        // u[col] partial over hp-half (split-K x2)
        {
            float a = 0.0f;
#pragma unroll
            for (int q = 0; q < HID / 2; q++) {
                int hp = half * (HID / 2) + q;
                a = fmaf(r[hp], __ldg(&W2[hp * HID + col]), a);
            }
            part[t] = a;
        }
        __syncthreads();
        if (t < HID) v[t] = fmaxf(part[t] + part[t + HID], 0.0f);
        __syncthreads();

        // V slice co = bid*128 + col (split-K x2)
        {
            int co = bid * HID + col;
            float a = 0.0f;
#pragma unroll
            for (int q = 0; q < HID / 2; q++) {
                int h = half * (HID / 2) + q;
                a = fmaf(v[h], __ldg(&W3[h * NCO + co]), a);
            }
            part[t] = a;
        }
        __syncthreads();
        if (t < HID) g_V[bid * HID + t] = part[t] + part[t + HID];

        // publish: stores -> fence -> barrier -> one increment
        __threadfence();
        __syncthreads();
        if (t == 0) atomicAdd(&g_done, 1u);
        return;
    }

    // ===================== worker =====================
    __shared__ float Vs[NCO];
    __shared__ float aux[2 * HID];   // reused: split-K partials on fallback
    __shared__ float vsh[HID];
    __shared__ float red[8];
    __shared__ int   fast_s;

    const int w    = bid - NPREP;        // 0..511
    const int wid  = t >> 5;             // warp in block
    const int lane = t & 31;
    const int pos  = w * 8 + wid;        // < NPOS by construction
    const int b    = pos >> 11;
    const int i    = pos & (LSEQ - 1);
    const int K    = read_K(Kp);
    const int nv   = min(i, K);

    // ---- V-independent work first (overlaps with prep) ----
    const float* trow = times + b * LSEQ;
    float ti = __ldg(&trow[i]);
    float sp = 0.0f;
    for (int d = lane + 1; d <= nv; d += 32) sp += __ldg(&trow[i - d]);
#pragma unroll
    for (int o = 16; o > 0; o >>= 1) sp += __shfl_down_sync(0xffffffffu, sp, o);
    float S = (float)nv * ti - __shfl_sync(0xffffffffu, sp, 0);
    float f = __ldg(&feat[(size_t)pos * CIN + lane]);

    // ---- bounded TIGHT poll for prep (no nanosleep) ----
    if (t == 0) {
        int ok = 0;
        for (unsigned it = 0; it < SPIN_MAX; ++it) {
            if (ld_volatile_u32(&g_done) >= NPREP) { ok = 1; break; }
        }
        if (ok) { __threadfence(); fast_s = g_fast; }
        else    { fast_s = -1; }     // timeout -> self-compute V
    }
    __syncthreads();
    int fastpath = fast_s;

    if (fastpath >= 0) {
        // prep published: stage V from global
        for (int idx = t; idx < NCO; idx += 256) Vs[idx] = g_V[idx];
        __syncthreads();
    } else {
        // -------- self-compute fallback: bit-identical to prep's ordering ----
        const int col  = t & (HID - 1);
        const int half = t >> 7;
        if (t < HID) vsh[t] = fmaxf(W1[t], 0.0f);   // reuse vsh as r[]
        float tot = bias_l1(b1, b2, b3, t, red);
        fastpath = (tot == 0.0f) ? 1 : 0;
        __syncthreads();
        {
            float a = 0.0f;
#pragma unroll
            for (int q = 0; q < HID / 2; q++) {
                int hp = half * (HID / 2) + q;
                a = fmaf(vsh[hp], __ldg(&W2[hp * HID + col]), a);
            }
            aux[t] = a;
        }
        __syncthreads();
        float u_tmp = (t < HID) ? (aux[t] + aux[t + HID]) : 0.0f;
        __syncthreads();
        if (t < HID) vsh[t] = fmaxf(u_tmp, 0.0f);
        __syncthreads();
        for (int s = 0; s < NPREP; s++) {
            int co = s * HID + col;
            float a = 0.0f;
#pragma unroll
            for (int q = 0; q < HID / 2; q++) {
                int h = half * (HID / 2) + q;
                a = fmaf(vsh[h], __ldg(&W3[h * NCO + co]), a);
            }
            aux[t] = a;
            __syncthreads();
            if (t < HID) Vs[s * HID + t] = aux[t] + aux[t + HID];
            __syncthreads();
        }
    }

    if (fastpath) {
        float acc = 0.0f;
#pragma unroll
        for (int c = 0; c < CIN; c++)
            acc = fmaf(__shfl_sync(0xffffffffu, f, c), Vs[c * COUT + lane], acc);
        out[(size_t)pos * COUT + lane] = S * acc;
    } else {
        // ---------- exact nonzero-bias fallback (dead for ref inputs) ------
        __shared__ float h1s[16 * HID];
        __shared__ float hsum_s[HID];
        __shared__ float y2s[NCO];
        __shared__ float fs[CIN];
        __shared__ float dts[16];
        for (int p = 0; p < 8; p++) {
            int pos2 = w * 8 + p;
            int b2i  = pos2 >> 11;
            int i2   = pos2 & (LSEQ - 1);
            float ti2 = times[b2i * LSEQ + i2];
            if (t < CIN) fs[t] = feat[(size_t)pos2 * CIN + t];
            int nv2 = min(i2, K);

            float hsum = 0.0f;
            for (int k0 = 0; k0 < K; k0 += 16) {
                int kk = min(16, K - k0);
                __syncthreads();
                if (t < kk) {
                    int j = i2 - (k0 + t + 1);
                    if (j < 0) j = 0;
                    dts[t] = fmaxf(ti2 - times[b2i * LSEQ + j], 0.0f);
                }
                __syncthreads();
                if (t < HID)
                    for (int k = 0; k < kk; k++)
                        h1s[k * HID + t] = fmaxf(fmaf(dts[k], W1[t], b1[t]), 0.0f);
                __syncthreads();
                if (t < HID) {
                    float acc2[16];
#pragma unroll
                    for (int k = 0; k < 16; k++) acc2[k] = 0.0f;
                    for (int hp = 0; hp < HID; hp++) {
                        float wv = W2[hp * HID + t];
#pragma unroll
                        for (int k = 0; k < 16; k++)
                            acc2[k] = fmaf(h1s[k * HID + hp], wv, acc2[k]);
                    }
                    for (int k = 0; k < kk; k++)
                        if (i2 - (k0 + k + 1) >= 0)
                            hsum += fmaxf(acc2[k] + b2[t], 0.0f);
                }
            }
            if (t < HID) hsum_s[t] = hsum;
            __syncthreads();

            for (int j = t; j < NCO; j += 256) {
                float a = (float)nv2 * b3[j];
                for (int h = 0; h < HID; h++)
                    a = fmaf(hsum_s[h], W3[h * NCO + j], a);
                y2s[j] = a;
            }
            __syncthreads();
            if (t < COUT) {
                float a = 0.0f;
#pragma unroll
                for (int c = 0; c < CIN; c++) a = fmaf(fs[c], y2s[c * COUT + t], a);
                out[(size_t)pos2 * COUT + t] = a;
            }
            __syncthreads();
        }
    }

    // ---- epilogue: last worker resets counters for the next replay ----
    __syncthreads();
    if (t == 0) {
        __threadfence();
        unsigned old = atomicAdd(&g_wdone, 1u);
        if (old == NWORK - 1) {
            g_done  = 0u;
            g_wdone = 0u;
            __threadfence();
        }
    }
}

// ---------------------------------------------------------------------------
// kernel_launch: ONE graph node, allocation-free.
// Input order: times, features, W1, b1, W2, b2, W3, b3, kernel_size
// ---------------------------------------------------------------------------
extern "C" void kernel_launch(void* const* d_in, const int* in_sizes, int n_in,
                              void* d_out, int out_size) {
    const float* times = (const float*)d_in[0];
    const float* feat  = (const float*)d_in[1];
    const float* W1    = (const float*)d_in[2];
    const float* b1    = (const float*)d_in[3];
    const float* W2    = (const float*)d_in[4];
    const float* b2    = (const float*)d_in[5];
    const float* W3    = (const float*)d_in[6];
    const float* b3    = (const float*)d_in[7];
    const int*   Kp    = (n_in > 8) ? (const int*)d_in[8] : nullptr;
    float* out = (float*)d_out;

    fused_kernel<<<NBLK, 256>>>(times, feat, W1, b1, W2, b2, W3, b3, Kp, out);
}

// round 6
// speedup vs baseline: 1.0344x; 1.0344x over previous
#include <cuda_runtime.h>
#include <cuda_bf16.h>

// Fixed problem shapes (ContConv1d_29583734735380)
#define BSZ   2
#define LSEQ  2048
#define CIN   32
#define COUT  32
#define HID   128
#define NPOS  (BSZ * LSEQ)
#define NCO   (CIN * COUT)     // 1024
#define NPREP 8                // V-builder blocks (NCO / HID)
#define NWORKB 128             // worker blocks; 8 warps x 4 positions = 32/blk
#define PPW   4                // positions per warp
#define NBLK  (NPREP + NWORKB) // 136 blocks -> single wave, ~1 per SM
#define SPIN_MAX (1u << 14)    // bounded tight poll; then self-compute V

// Scratch (no device allocation allowed — __device__ globals; zero-init)
__device__ float    g_V[NCO];   // collapsed kernel matrix V[c*COUT+o]
__device__ int      g_fast;     // 1 iff all biases are exactly zero
__device__ unsigned g_done;     // prep blocks finished (reset each launch)
__device__ unsigned g_wdone;    // worker blocks finished (reset each launch)

__device__ __forceinline__ int read_K(const int* __restrict__ Kp) {
    int k = Kp ? __ldg(Kp) : 16;
    if (k < 1 || k > LSEQ) k = 16;   // guard odd metadata dtype
    return k;
}

__device__ __forceinline__ unsigned ld_volatile_u32(const unsigned* p) {
    unsigned v;
    asm volatile("ld.volatile.global.u32 %0, [%1];" : "=r"(v) : "l"(p));
    return v;
}

// Bias L1 partial over 256 threads; returns block-total (valid on all threads).
__device__ __forceinline__ float bias_l1(const float* __restrict__ b1,
                                         const float* __restrict__ b2,
                                         const float* __restrict__ b3,
                                         int t, float* red8 /* >=8 floats */) {
    float s = 0.0f;
    for (int idx = t; idx < 2 * HID + NCO; idx += 256) {
        float x = (idx < HID)     ? b1[idx]
                : (idx < 2 * HID) ? b2[idx - HID]
                :                   b3[idx - 2 * HID];
        s += fabsf(x);
    }
#pragma unroll
    for (int o = 16; o > 0; o >>= 1) s += __shfl_down_sync(0xffffffffu, s, o);
    if ((t & 31) == 0) red8[t >> 5] = s;
    __syncthreads();
    float tot = 0.0f;
#pragma unroll
    for (int w = 0; w < 8; w++) tot += red8[w];
    return tot;
}

// ---------------------------------------------------------------------------
// ONE kernel, 136 blocks. blocks [0,8): build V + bias check, publish.
// blocks [8,136): 8 warps x 4 positions each; V-independent work first,
// bounded tight-poll on g_done (self-compute V on timeout), then
// out = S * (f @ V). Exact nonzero-bias fallback inlined (dead for ref).
// ---------------------------------------------------------------------------
__global__ void __launch_bounds__(256, 4) fused_kernel(
        const float* __restrict__ times,
        const float* __restrict__ feat,
        const float* __restrict__ W1,
        const float* __restrict__ b1,
        const float* __restrict__ W2,
        const float* __restrict__ b2,
        const float* __restrict__ W3,
        const float* __restrict__ b3,
        const int*   __restrict__ Kp,
        float*       __restrict__ out) {
    const int t   = threadIdx.x;   // 0..255
    const int bid = blockIdx.x;

    if (bid < NPREP) {
        // ===================== prep =====================
        __shared__ float r[HID];
        __shared__ float part[2 * HID];
        __shared__ float v[HID];
        __shared__ float red[8];
        const int col  = t & (HID - 1);
        const int half = t >> 7;

        if (t < HID) r[t] = fmaxf(W1[t], 0.0f);

        if (bid == 0) {
            float tot = bias_l1(b1, b2, b3, t, red);
            if (t == 0) g_fast = (tot == 0.0f) ? 1 : 0;
        } else {
            __syncthreads();  // match bias_l1's internal barrier
        }
        __syncthreads();

        // u[col] partial over hp-half (split-K x2)
        {
            float a = 0.0f;
#pragma unroll
            for (int q = 0; q < HID / 2; q++) {
                int hp = half * (HID / 2) + q;
                a = fmaf(r[hp], __ldg(&W2[hp * HID + col]), a);
            }
            part[t] = a;
        }
        __syncthreads();
        if (t < HID) v[t] = fmaxf(part[t] + part[t + HID], 0.0f);
        __syncthreads();

        // V slice co = bid*128 + col (split-K x2)
        {
            int co = bid * HID + col;
            float a = 0.0f;
#pragma unroll
            for (int q = 0; q < HID / 2; q++) {
                int h = half * (HID / 2) + q;
                a = fmaf(v[h], __ldg(&W3[h * NCO + co]), a);
            }
            part[t] = a;
        }
        __syncthreads();
        if (t < HID) g_V[bid * HID + t] = part[t] + part[t + HID];

        // publish: stores -> fence -> barrier -> one increment
        __threadfence();
        __syncthreads();
        if (t == 0) atomicAdd(&g_done, 1u);
        return;
    }

    // ===================== worker =====================
    __shared__ float Vs[NCO];
    __shared__ float aux[2 * HID];   // split-K partials on self-compute path
    __shared__ float vsh[HID];
    __shared__ float red[8];
    __shared__ int   fast_s;

    const int w    = bid - NPREP;        // 0..127
    const int wid  = t >> 5;             // warp in block
    const int lane = t & 31;
    const int gw   = w * 8 + wid;        // global warp 0..1023
    const int K    = read_K(Kp);

    // ---- V-independent work first (overlaps with prep) ----
    float Sv[PPW], fv[PPW];
#pragma unroll
    for (int p = 0; p < PPW; p++) {
        int pos = gw * PPW + p;          // < NPOS
        int b   = pos >> 11;
        int i   = pos & (LSEQ - 1);
        int nv  = min(i, K);
        const float* trow = times + b * LSEQ;
        float ti = __ldg(&trow[i]);
        float sp = 0.0f;
        for (int d = lane + 1; d <= nv; d += 32) sp += __ldg(&trow[i - d]);
#pragma unroll
        for (int o = 16; o > 0; o >>= 1) sp += __shfl_down_sync(0xffffffffu, sp, o);
        Sv[p] = (float)nv * ti - __shfl_sync(0xffffffffu, sp, 0);
        fv[p] = __ldg(&feat[(size_t)pos * CIN + lane]);
    }

    // ---- bounded TIGHT poll for prep ----
    if (t == 0) {
        int ok = 0;
        for (unsigned it = 0; it < SPIN_MAX; ++it) {
            if (ld_volatile_u32(&g_done) >= NPREP) { ok = 1; break; }
        }
        if (ok) { __threadfence(); fast_s = g_fast; }
        else    { fast_s = -1; }     // timeout -> self-compute V
    }
    __syncthreads();
    int fastpath = fast_s;

    if (fastpath >= 0) {
        for (int idx = t; idx < NCO; idx += 256) Vs[idx] = g_V[idx];
        __syncthreads();
    } else {
        // -------- self-compute V: bit-identical to prep's ordering ----------
        const int col  = t & (HID - 1);
        const int half = t >> 7;
        if (t < HID) vsh[t] = fmaxf(W1[t], 0.0f);
        float tot = bias_l1(b1, b2, b3, t, red);
        fastpath = (tot == 0.0f) ? 1 : 0;
        __syncthreads();
        {
            float a = 0.0f;
#pragma unroll
            for (int q = 0; q < HID / 2; q++) {
                int hp = half * (HID / 2) + q;
                a = fmaf(vsh[hp], __ldg(&W2[hp * HID + col]), a);
            }
            aux[t] = a;
        }
        __syncthreads();
        float u_tmp = (t < HID) ? (aux[t] + aux[t + HID]) : 0.0f;
        __syncthreads();
        if (t < HID) vsh[t] = fmaxf(u_tmp, 0.0f);
        __syncthreads();
        for (int s = 0; s < NPREP; s++) {
            int co = s * HID + col;
            float a = 0.0f;
#pragma unroll
            for (int q = 0; q < HID / 2; q++) {
                int h = half * (HID / 2) + q;
                a = fmaf(vsh[h], __ldg(&W3[h * NCO + co]), a);
            }
            aux[t] = a;
            __syncthreads();
            if (t < HID) Vs[s * HID + t] = aux[t] + aux[t + HID];
            __syncthreads();
        }
    }

    if (fastpath) {
#pragma unroll
        for (int p = 0; p < PPW; p++) {
            float acc = 0.0f;
#pragma unroll
            for (int c = 0; c < CIN; c++)
                acc = fmaf(__shfl_sync(0xffffffffu, fv[p], c),
                           Vs[c * COUT + lane], acc);
            int pos = gw * PPW + p;
            out[(size_t)pos * COUT + lane] = Sv[p] * acc;
        }
    } else {
        // ---------- exact nonzero-bias fallback (dead for ref inputs) ------
        __shared__ float h1s[16 * HID];
        __shared__ float hsum_s[HID];
        __shared__ float y2s[NCO];
        __shared__ float fs[CIN];
        __shared__ float dts[16];
        for (int p = 0; p < 8 * PPW; p++) {
            int pos2 = w * (8 * PPW) + p;
            int b2i  = pos2 >> 11;
            int i2   = pos2 & (LSEQ - 1);
            float ti2 = times[b2i * LSEQ + i2];
            if (t < CIN) fs[t] = feat[(size_t)pos2 * CIN + t];
            int nv2 = min(i2, K);

            float hsum = 0.0f;
            for (int k0 = 0; k0 < K; k0 += 16) {
                int kk = min(16, K - k0);
                __syncthreads();
                if (t < kk) {
                    int j = i2 - (k0 + t + 1);
                    if (j < 0) j = 0;
                    dts[t] = fmaxf(ti2 - times[b2i * LSEQ + j], 0.0f);
                }
                __syncthreads();
                if (t < HID)
                    for (int k = 0; k < kk; k++)
                        h1s[k * HID + t] = fmaxf(fmaf(dts[k], W1[t], b1[t]), 0.0f);
                __syncthreads();
                if (t < HID) {
                    float acc2[16];
#pragma unroll
                    for (int k = 0; k < 16; k++) acc2[k] = 0.0f;
                    for (int hp = 0; hp < HID; hp++) {
                        float wv = W2[hp * HID + t];
#pragma unroll
                        for (int k = 0; k < 16; k++)
                            acc2[k] = fmaf(h1s[k * HID + hp], wv, acc2[k]);
                    }
                    for (int k = 0; k < kk; k++)
                        if (i2 - (k0 + k + 1) >= 0)
                            hsum += fmaxf(acc2[k] + b2[t], 0.0f);
                }
            }
            if (t < HID) hsum_s[t] = hsum;
            __syncthreads();

            for (int j = t; j < NCO; j += 256) {
                float a = (float)nv2 * b3[j];
                for (int h = 0; h < HID; h++)
                    a = fmaf(hsum_s[h], W3[h * NCO + j], a);
                y2s[j] = a;
            }
            __syncthreads();
            if (t < COUT) {
                float a = 0.0f;
#pragma unroll
                for (int c = 0; c < CIN; c++) a = fmaf(fs[c], y2s[c * COUT + t], a);
                out[(size_t)pos2 * COUT + t] = a;
            }
            __syncthreads();
        }
    }

    // ---- epilogue: last worker resets counters for the next replay ----
    __syncthreads();
    if (t == 0) {
        __threadfence();
        unsigned old = atomicAdd(&g_wdone, 1u);
        if (old == NWORKB - 1) {
            g_done  = 0u;
            g_wdone = 0u;
            __threadfence();
        }
    }
}

// ---------------------------------------------------------------------------
// kernel_launch: ONE graph node, allocation-free.
// Input order: times, features, W1, b1, W2, b2, W3, b3, kernel_size
// ---------------------------------------------------------------------------
extern "C" void kernel_launch(void* const* d_in, const int* in_sizes, int n_in,
                              void* d_out, int out_size) {
    const float* times = (const float*)d_in[0];
    const float* feat  = (const float*)d_in[1];
    const float* W1    = (const float*)d_in[2];
    const float* b1    = (const float*)d_in[3];
    const float* W2    = (const float*)d_in[4];
    const float* b2    = (const float*)d_in[5];
    const float* W3    = (const float*)d_in[6];
    const float* b3    = (const float*)d_in[7];
    const int*   Kp    = (n_in > 8) ? (const int*)d_in[8] : nullptr;
    float* out = (float*)d_out;

    fused_kernel<<<NBLK, 256>>>(times, feat, W1, b1, W2, b2, W3, b3, Kp, out);
}

// round 7
// speedup vs baseline: 1.2382x; 1.1971x over previous
#include <cuda_runtime.h>
#include <cuda_bf16.h>

// Fixed problem shapes (ContConv1d_29583734735380)
#define BSZ   2
#define LSEQ  2048
#define CIN   32
#define COUT  32
#define HID   128
#define NPOS  (BSZ * LSEQ)
#define NCO   (CIN * COUT)     // 1024
#define NVB   8                // V-builder blocks (NCO / HID)
#define NPREP 9                // 8 V-blocks + 1 bias block
#define NWORKB 128             // worker blocks; 8 warps x 4 positions
#define PPW   4                // positions per warp
#define NBLK  (NPREP + NWORKB) // 137 blocks -> single wave
#define SPIN_MAX (1u << 14)    // bounded tight poll; then self-compute V

// g_done encoding: each V-block adds 1 (8 total); bias block adds 8, plus 256
// if biases are nonzero. Ready <=> (g_done & 0xFF) == 16. Fast <=> g_done<256.
#define READY_MASK 0xFFu
#define READY_VAL  16u
#define SLOW_BIT   256u

// Scratch (no device allocation allowed — __device__ globals; zero-init)
__device__ float    g_V[NCO];   // collapsed kernel matrix V[c*COUT+o]
__device__ unsigned g_done;     // readiness+fast word (reset each launch)
__device__ unsigned g_wdone;    // worker blocks finished (reset each launch)

__device__ __forceinline__ int read_K(const int* __restrict__ Kp) {
    int k = Kp ? __ldg(Kp) : 16;
    if (k < 1 || k > LSEQ) k = 16;   // guard odd metadata dtype
    return k;
}

__device__ __forceinline__ unsigned ld_volatile_u32(const unsigned* p) {
    unsigned v;
    asm volatile("ld.volatile.global.u32 %0, [%1];" : "=r"(v) : "l"(p));
    return v;
}

// Bias L1 partial over 256 threads; returns block-total (valid on all threads).
__device__ __forceinline__ float bias_l1(const float* __restrict__ b1,
                                         const float* __restrict__ b2,
                                         const float* __restrict__ b3,
                                         int t, float* red8 /* >=8 floats */) {
    float s = 0.0f;
    for (int idx = t; idx < 2 * HID + NCO; idx += 256) {
        float x = (idx < HID)     ? b1[idx]
                : (idx < 2 * HID) ? b2[idx - HID]
                :                   b3[idx - 2 * HID];
        s += fabsf(x);
    }
#pragma unroll
    for (int o = 16; o > 0; o >>= 1) s += __shfl_down_sync(0xffffffffu, s, o);
    if ((t & 31) == 0) red8[t >> 5] = s;
    __syncthreads();
    float tot = 0.0f;
#pragma unroll
    for (int w = 0; w < 8; w++) tot += red8[w];
    return tot;
}

// ---------------------------------------------------------------------------
// ONE kernel, 137 blocks.
//   blocks [0,8):  V chain only (no bias logic) -> g_V slice, add 1 to g_done
//   block  8:      bias L1 check -> add 8 (+256 if nonzero) to g_done
//   blocks [9,137): 8 warps x 4 positions; prologue first, one-word poll,
//                   float4 V staging, dot; self-compute V on poll timeout;
//                   exact nonzero-bias fallback inlined (dead for ref).
// ---------------------------------------------------------------------------
__global__ void __launch_bounds__(256, 4) fused_kernel(
        const float* __restrict__ times,
        const float* __restrict__ feat,
        const float* __restrict__ W1,
        const float* __restrict__ b1,
        const float* __restrict__ W2,
        const float* __restrict__ b2,
        const float* __restrict__ W3,
        const float* __restrict__ b3,
        const int*   __restrict__ Kp,
        float*       __restrict__ out) {
    const int t   = threadIdx.x;   // 0..255
    const int bid = blockIdx.x;

    if (bid < NVB) {
        // ===================== V-builder prep =====================
        __shared__ float r[HID];
        __shared__ float part[2 * HID];
        __shared__ float v[HID];
        const int col  = t & (HID - 1);
        const int half = t >> 7;

        if (t < HID) r[t] = fmaxf(W1[t], 0.0f);
        __syncthreads();

        // u[col] partial over hp-half (split-K x2)
        {
            float a = 0.0f;
#pragma unroll
            for (int q = 0; q < HID / 2; q++) {
                int hp = half * (HID / 2) + q;
                a = fmaf(r[hp], __ldg(&W2[hp * HID + col]), a);
            }
            part[t] = a;
        }
        __syncthreads();
        if (t < HID) v[t] = fmaxf(part[t] + part[t + HID], 0.0f);
        __syncthreads();

        // V slice co = bid*128 + col (split-K x2)
        {
            int co = bid * HID + col;
            float a = 0.0f;
#pragma unroll
            for (int q = 0; q < HID / 2; q++) {
                int h = half * (HID / 2) + q;
                a = fmaf(v[h], __ldg(&W3[h * NCO + co]), a);
            }
            part[t] = a;
        }
        __syncthreads();
        if (t < HID) g_V[bid * HID + t] = part[t] + part[t + HID];

        __threadfence();
        __syncthreads();
        if (t == 0) atomicAdd(&g_done, 1u);
        return;
    }

    if (bid == NVB) {
        // ===================== bias-check prep =====================
        __shared__ float red[8];
        float tot = bias_l1(b1, b2, b3, t, red);
        __syncthreads();
        if (t == 0) {
            unsigned add = 8u + ((tot != 0.0f) ? SLOW_BIT : 0u);
            __threadfence();
            atomicAdd(&g_done, add);
        }
        return;
    }

    // ===================== worker =====================
    __shared__ float Vs[NCO];
    __shared__ float aux[2 * HID];   // split-K partials on self-compute path
    __shared__ float vsh[HID];
    __shared__ float red[8];
    __shared__ int   fast_s;

    const int w    = bid - NPREP;        // 0..127
    const int wid  = t >> 5;             // warp in block
    const int lane = t & 31;
    const int gw   = w * 8 + wid;        // global warp 0..1023
    const int K    = read_K(Kp);

    // ---- V-independent work first (overlaps with prep) ----
    float Sv[PPW], fv[PPW];
#pragma unroll
    for (int p = 0; p < PPW; p++) {
        int pos = gw * PPW + p;          // < NPOS
        int b   = pos >> 11;
        int i   = pos & (LSEQ - 1);
        int nv  = min(i, K);
        const float* trow = times + b * LSEQ;
        float ti = __ldg(&trow[i]);
        float sp = 0.0f;
        for (int d = lane + 1; d <= nv; d += 32) sp += __ldg(&trow[i - d]);
#pragma unroll
        for (int o = 16; o > 0; o >>= 1) sp += __shfl_down_sync(0xffffffffu, sp, o);
        Sv[p] = (float)nv * ti - __shfl_sync(0xffffffffu, sp, 0);
        fv[p] = __ldg(&feat[(size_t)pos * CIN + lane]);
    }

    // ---- bounded TIGHT poll: one word gives readiness AND fastpath ----
    if (t == 0) {
        int fs = -1;                       // timeout -> self-compute V
        for (unsigned it = 0; it < SPIN_MAX; ++it) {
            unsigned v = ld_volatile_u32(&g_done);
            if ((v & READY_MASK) == READY_VAL) {
                fs = (v < SLOW_BIT) ? 1 : 0;
                break;
            }
        }
        if (fs >= 0) __threadfence();      // acquire for g_V
        fast_s = fs;
    }
    __syncthreads();
    int fastpath = fast_s;

    if (fastpath >= 0) {
        // stage V: one float4 per thread (256 x 16B = 4KB)
        const float4* src = (const float4*)g_V;
        ((float4*)Vs)[t] = src[t];
        __syncthreads();
    } else {
        // -------- self-compute V: same ordering as prep ---------------------
        const int col  = t & (HID - 1);
        const int half = t >> 7;
        if (t < HID) vsh[t] = fmaxf(W1[t], 0.0f);
        float tot = bias_l1(b1, b2, b3, t, red);
        fastpath = (tot == 0.0f) ? 1 : 0;
        __syncthreads();
        {
            float a = 0.0f;
#pragma unroll
            for (int q = 0; q < HID / 2; q++) {
                int hp = half * (HID / 2) + q;
                a = fmaf(vsh[hp], __ldg(&W2[hp * HID + col]), a);
            }
            aux[t] = a;
        }
        __syncthreads();
        float u_tmp = (t < HID) ? (aux[t] + aux[t + HID]) : 0.0f;
        __syncthreads();
        if (t < HID) vsh[t] = fmaxf(u_tmp, 0.0f);
        __syncthreads();
        for (int s = 0; s < NVB; s++) {
            int co = s * HID + col;
            float a = 0.0f;
#pragma unroll
            for (int q = 0; q < HID / 2; q++) {
                int h = half * (HID / 2) + q;
                a = fmaf(vsh[h], __ldg(&W3[h * NCO + co]), a);
            }
            aux[t] = a;
            __syncthreads();
            if (t < HID) Vs[s * HID + t] = aux[t] + aux[t + HID];
            __syncthreads();
        }
    }

    if (fastpath) {
#pragma unroll
        for (int p = 0; p < PPW; p++) {
            float acc = 0.0f;
#pragma unroll
            for (int c = 0; c < CIN; c++)
                acc = fmaf(__shfl_sync(0xffffffffu, fv[p], c),
                           Vs[c * COUT + lane], acc);
            int pos = gw * PPW + p;
            out[(size_t)pos * COUT + lane] = Sv[p] * acc;
        }
    } else {
        // ---------- exact nonzero-bias fallback (dead for ref inputs) ------
        __shared__ float h1s[16 * HID];
        __shared__ float hsum_s[HID];
        __shared__ float y2s[NCO];
        __shared__ float fs[CIN];
        __shared__ float dts[16];
        for (int p = 0; p < 8 * PPW; p++) {
            int pos2 = w * (8 * PPW) + p;
            int b2i  = pos2 >> 11;
            int i2   = pos2 & (LSEQ - 1);
            float ti2 = times[b2i * LSEQ + i2];
            if (t < CIN) fs[t] = feat[(size_t)pos2 * CIN + t];
            int nv2 = min(i2, K);

            float hsum = 0.0f;
            for (int k0 = 0; k0 < K; k0 += 16) {
                int kk = min(16, K - k0);
                __syncthreads();
                if (t < kk) {
                    int j = i2 - (k0 + t + 1);
                    if (j < 0) j = 0;
                    dts[t] = fmaxf(ti2 - times[b2i * LSEQ + j], 0.0f);
                }
                __syncthreads();
                if (t < HID)
                    for (int k = 0; k < kk; k++)
                        h1s[k * HID + t] = fmaxf(fmaf(dts[k], W1[t], b1[t]), 0.0f);
                __syncthreads();
                if (t < HID) {
                    float acc2[16];
#pragma unroll
                    for (int k = 0; k < 16; k++) acc2[k] = 0.0f;
                    for (int hp = 0; hp < HID; hp++) {
                        float wv = W2[hp * HID + t];
#pragma unroll
                        for (int k = 0; k < 16; k++)
                            acc2[k] = fmaf(h1s[k * HID + hp], wv, acc2[k]);
                    }
                    for (int k = 0; k < kk; k++)
                        if (i2 - (k0 + k + 1) >= 0)
                            hsum += fmaxf(acc2[k] + b2[t], 0.0f);
                }
            }
            if (t < HID) hsum_s[t] = hsum;
            __syncthreads();

            for (int j = t; j < NCO; j += 256) {
                float a = (float)nv2 * b3[j];
                for (int h = 0; h < HID; h++)
                    a = fmaf(hsum_s[h], W3[h * NCO + j], a);
                y2s[j] = a;
            }
            __syncthreads();
            if (t < COUT) {
                float a = 0.0f;
#pragma unroll
                for (int c = 0; c < CIN; c++) a = fmaf(fs[c], y2s[c * COUT + t], a);
                out[(size_t)pos2 * COUT + t] = a;
            }
            __syncthreads();
        }
    }

    // ---- epilogue: last worker resets counters for the next replay ----
    __syncthreads();
    if (t == 0) {
        __threadfence();
        unsigned old = atomicAdd(&g_wdone, 1u);
        if (old == NWORKB - 1) {
            g_done  = 0u;
            g_wdone = 0u;
            __threadfence();
        }
    }
}

// ---------------------------------------------------------------------------
// kernel_launch: ONE graph node, allocation-free.
// Input order: times, features, W1, b1, W2, b2, W3, b3, kernel_size
// ---------------------------------------------------------------------------
extern "C" void kernel_launch(void* const* d_in, const int* in_sizes, int n_in,
                              void* d_out, int out_size) {
    const float* times = (const float*)d_in[0];
    const float* feat  = (const float*)d_in[1];
    const float* W1    = (const float*)d_in[2];
    const float* b1    = (const float*)d_in[3];
    const float* W2    = (const float*)d_in[4];
    const float* b2    = (const float*)d_in[5];
    const float* W3    = (const float*)d_in[6];
    const float* b3    = (const float*)d_in[7];
    const int*   Kp    = (n_in > 8) ? (const int*)d_in[8] : nullptr;
    float* out = (float*)d_out;

    fused_kernel<<<NBLK, 256>>>(times, feat, W1, b1, W2, b2, W3, b3, Kp, out);
}

// round 8
// speedup vs baseline: 1.4467x; 1.1684x over previous
#include <cuda_runtime.h>
#include <cuda_bf16.h>

// Fixed problem shapes (ContConv1d_29583734735380)
#define BSZ   2
#define LSEQ  2048
#define CIN   32
#define COUT  32
#define HID   128
#define NPOS  (BSZ * LSEQ)
#define NCO   (CIN * COUT)     // 1024
#define NVB   8                // V-builder blocks (NCO / HID)
#define NPREP 9                // 8 V-blocks + 1 bias block
#define NWORKB 128             // worker blocks; 8 warps x 4 positions
#define PPW   4                // positions per warp
#define NBLK  (NPREP + NWORKB) // 137 blocks -> single wave
#define SPIN_MAX (1u << 14)    // bounded tight poll; then self-compute V

// g_done encoding: each V-block adds 1 (8 total); bias block adds 8, plus 256
// if biases are nonzero. Ready <=> (g_done & 0xFF) == 16. Fast <=> g_done<256.
#define READY_MASK 0xFFu
#define READY_VAL  16u
#define SLOW_BIT   256u

// Scratch (no device allocation allowed — __device__ globals; zero-init)
__device__ float    g_V[NCO];   // collapsed kernel matrix V[c*COUT+o]
__device__ unsigned g_done;     // readiness+fast word (reset each launch)
__device__ unsigned g_wdone;    // worker blocks finished (reset each launch)

__device__ __forceinline__ int read_K(const int* __restrict__ Kp) {
    int k = Kp ? __ldg(Kp) : 16;
    if (k < 1 || k > LSEQ) k = 16;   // guard odd metadata dtype
    return k;
}

__device__ __forceinline__ unsigned ld_acquire_u32(const unsigned* p) {
    unsigned v;
    asm volatile("ld.acquire.gpu.global.u32 %0, [%1];" : "=r"(v) : "l"(p) : "memory");
    return v;
}

__device__ __forceinline__ void red_add_release_u32(unsigned* p, unsigned v) {
    asm volatile("red.release.gpu.global.add.u32 [%0], %1;" :: "l"(p), "r"(v) : "memory");
}

// Bias L1 partial over 256 threads; returns block-total (valid on all threads).
__device__ __forceinline__ float bias_l1(const float* __restrict__ b1,
                                         const float* __restrict__ b2,
                                         const float* __restrict__ b3,
                                         int t, float* red8 /* >=8 floats */) {
    float s = 0.0f;
    for (int idx = t; idx < 2 * HID + NCO; idx += 256) {
        float x = (idx < HID)     ? b1[idx]
                : (idx < 2 * HID) ? b2[idx - HID]
                :                   b3[idx - 2 * HID];
        s += fabsf(x);
    }
#pragma unroll
    for (int o = 16; o > 0; o >>= 1) s += __shfl_down_sync(0xffffffffu, s, o);
    if ((t & 31) == 0) red8[t >> 5] = s;
    __syncthreads();
    float tot = 0.0f;
#pragma unroll
    for (int w = 0; w < 8; w++) tot += red8[w];
    return tot;
}

// ---------------------------------------------------------------------------
// ONE kernel, 137 blocks, single wave.
//   blocks [0,8):  register-prefetched V chain -> g_V slice, release-add 1
//   block  8:      bias L1 check -> add 8 (+256 if nonzero)
//   blocks [9,137): 8 warps x 4 positions; clamped single-load window (K off
//                   the load path), acquire-poll, register-resident V dot.
// ---------------------------------------------------------------------------
__global__ void __launch_bounds__(256, 1) fused_kernel(
        const float* __restrict__ times,
        const float* __restrict__ feat,
        const float* __restrict__ W1,
        const float* __restrict__ b1,
        const float* __restrict__ W2,
        const float* __restrict__ b2,
        const float* __restrict__ W3,
        const float* __restrict__ b3,
        const int*   __restrict__ Kp,
        float*       __restrict__ out) {
    const int t   = threadIdx.x;   // 0..255
    const int bid = blockIdx.x;

    if (bid < NVB) {
        // ===================== V-builder prep (register prefetch) ==========
        __shared__ float r[HID];
        __shared__ float part[2 * HID];
        __shared__ float v[HID];
        const int col  = t & (HID - 1);
        const int half = t >> 7;
        const int hb   = half * (HID / 2);
        const int co   = bid * HID + col;

        if (t < HID) r[t] = fmaxf(W1[t], 0.0f);   // issue first

        // prefetch ALL W2/W3 operands -> one overlapped load phase
        float w2r[HID / 2], w3r[HID / 2];
#pragma unroll
        for (int q = 0; q < HID / 2; q++)
            w2r[q] = __ldg(&W2[(hb + q) * HID + col]);
#pragma unroll
        for (int q = 0; q < HID / 2; q++)
            w3r[q] = __ldg(&W3[(hb + q) * NCO + co]);
        __syncthreads();

        // u-stage: dual accumulator (order mirrored in self-compute fallback)
        {
            float a0 = 0.0f, a1 = 0.0f;
#pragma unroll
            for (int q = 0; q < HID / 4; q++) {
                a0 = fmaf(r[hb + 2 * q],     w2r[2 * q],     a0);
                a1 = fmaf(r[hb + 2 * q + 1], w2r[2 * q + 1], a1);
            }
            part[t] = a0 + a1;
        }
        __syncthreads();
        if (t < HID) v[t] = fmaxf(part[t] + part[t + HID], 0.0f);
        __syncthreads();

        // V-stage
        {
            float a0 = 0.0f, a1 = 0.0f;
#pragma unroll
            for (int q = 0; q < HID / 4; q++) {
                a0 = fmaf(v[hb + 2 * q],     w3r[2 * q],     a0);
                a1 = fmaf(v[hb + 2 * q + 1], w3r[2 * q + 1], a1);
            }
            part[t] = a0 + a1;
        }
        __syncthreads();
        if (t < HID) g_V[bid * HID + t] = part[t] + part[t + HID];

        __threadfence();
        __syncthreads();
        if (t == 0) red_add_release_u32(&g_done, 1u);
        return;
    }

    if (bid == NVB) {
        // ===================== bias-check prep =====================
        __shared__ float red[8];
        float tot = bias_l1(b1, b2, b3, t, red);
        __syncthreads();
        if (t == 0)
            atomicAdd(&g_done, 8u + ((tot != 0.0f) ? SLOW_BIT : 0u));
        return;
    }

    // ===================== worker =====================
    __shared__ float Vs[NCO];        // fallback paths only
    __shared__ float aux[2 * HID];
    __shared__ float vsh[HID];
    __shared__ float red[8];
    __shared__ int   fast_s;

    const int w    = bid - NPREP;        // 0..127
    const int wid  = t >> 5;
    const int lane = t & 31;
    const int gw   = w * 8 + wid;        // global warp 0..1023
    const int K    = read_K(Kp);         // load issued here; used only later

    // ---- all independent loads issue immediately (K not needed yet) ----
    float ti[PPW], tw[PPW], fv[PPW];
#pragma unroll
    for (int p = 0; p < PPW; p++) {
        int pos = gw * PPW + p;
        int b   = pos >> 11;
        int i   = pos & (LSEQ - 1);
        const float* trow = times + b * LSEQ;
        ti[p] = __ldg(&trow[i]);
        int j = i - 1 - lane; if (j < 0) j = 0;   // clamped window load
        tw[p] = __ldg(&trow[j]);
        fv[p] = __ldg(&feat[(size_t)pos * CIN + lane]);
    }

    // ---- S[p] = nv*ti - sum(window), mask applied after K arrives ----
    float Sv[PPW];
#pragma unroll
    for (int p = 0; p < PPW; p++) {
        int pos = gw * PPW + p;
        int b   = pos >> 11;
        int i   = pos & (LSEQ - 1);
        int nv  = min(i, K);
        float x = (lane < nv) ? tw[p] : 0.0f;
        if (K > 31) {                    // dead for reference K=16
            const float* trow = times + b * LSEQ;
            for (int d = lane + 33; d <= nv; d += 32) x += __ldg(&trow[i - d]);
        }
#pragma unroll
        for (int o = 16; o > 0; o >>= 1) x += __shfl_xor_sync(0xffffffffu, x, o);
        Sv[p] = (float)nv * ti[p] - x;   // x identical in all lanes (butterfly)
    }

    // ---- acquire-poll: one word gives readiness AND fastpath ----
    if (t == 0) {
        int fs = -1;                     // timeout -> self-compute V
        for (unsigned it = 0; it < SPIN_MAX; ++it) {
            unsigned v = ld_acquire_u32(&g_done);
            if ((v & READY_MASK) == READY_VAL) { fs = (v < SLOW_BIT) ? 1 : 0; break; }
        }
        fast_s = fs;
    }
    __syncthreads();
    int fastpath = fast_s;

    float vr[CIN];                       // register-resident V column slice
    if (fastpath >= 0) {
        // direct coalesced loads; ordered after the acquire by the barrier
#pragma unroll
        for (int c = 0; c < CIN; c++) vr[c] = g_V[c * COUT + lane];
    } else {
        // -------- self-compute V: FP order identical to prep ----------------
        const int col  = t & (HID - 1);
        const int half = t >> 7;
        const int hb   = half * (HID / 2);
        if (t < HID) vsh[t] = fmaxf(W1[t], 0.0f);
        float tot = bias_l1(b1, b2, b3, t, red);
        fastpath = (tot == 0.0f) ? 1 : 0;
        __syncthreads();
        {
            float a0 = 0.0f, a1 = 0.0f;
#pragma unroll
            for (int q = 0; q < HID / 4; q++) {
                a0 = fmaf(vsh[hb + 2 * q],     __ldg(&W2[(hb + 2 * q) * HID + col]),     a0);
                a1 = fmaf(vsh[hb + 2 * q + 1], __ldg(&W2[(hb + 2 * q + 1) * HID + col]), a1);
            }
            aux[t] = a0 + a1;
        }
        __syncthreads();
        float u_tmp = (t < HID) ? (aux[t] + aux[t + HID]) : 0.0f;
        __syncthreads();
        if (t < HID) vsh[t] = fmaxf(u_tmp, 0.0f);
        __syncthreads();
        for (int s = 0; s < NVB; s++) {
            int co = s * HID + col;
            float a0 = 0.0f, a1 = 0.0f;
#pragma unroll
            for (int q = 0; q < HID / 4; q++) {
                a0 = fmaf(vsh[hb + 2 * q],     __ldg(&W3[(hb + 2 * q) * NCO + co]),     a0);
                a1 = fmaf(vsh[hb + 2 * q + 1], __ldg(&W3[(hb + 2 * q + 1) * NCO + co]), a1);
            }
            aux[t] = a0 + a1;
            __syncthreads();
            if (t < HID) Vs[s * HID + t] = aux[t] + aux[t + HID];
            __syncthreads();
        }
#pragma unroll
        for (int c = 0; c < CIN; c++) vr[c] = Vs[c * COUT + lane];
    }

    if (fastpath) {
#pragma unroll
        for (int p = 0; p < PPW; p++) {
            float acc = 0.0f;
#pragma unroll
            for (int c = 0; c < CIN; c++)
                acc = fmaf(__shfl_sync(0xffffffffu, fv[p], c), vr[c], acc);
            int pos = gw * PPW + p;
            out[(size_t)pos * COUT + lane] = Sv[p] * acc;
        }
    } else {
        // ---------- exact nonzero-bias fallback (dead for ref inputs) ------
        __shared__ float h1s[16 * HID];
        __shared__ float hsum_s[HID];
        __shared__ float y2s[NCO];
        __shared__ float fs2[CIN];
        __shared__ float dts[16];
        for (int p = 0; p < 8 * PPW; p++) {
            int pos2 = w * (8 * PPW) + p;
            int b2i  = pos2 >> 11;
            int i2   = pos2 & (LSEQ - 1);
            float ti2 = times[b2i * LSEQ + i2];
            if (t < CIN) fs2[t] = feat[(size_t)pos2 * CIN + t];
            int nv2 = min(i2, K);

            float hsum = 0.0f;
            for (int k0 = 0; k0 < K; k0 += 16) {
                int kk = min(16, K - k0);
                __syncthreads();
                if (t < kk) {
                    int j = i2 - (k0 + t + 1);
                    if (j < 0) j = 0;
                    dts[t] = fmaxf(ti2 - times[b2i * LSEQ + j], 0.0f);
                }
                __syncthreads();
                if (t < HID)
                    for (int k = 0; k < kk; k++)
                        h1s[k * HID + t] = fmaxf(fmaf(dts[k], W1[t], b1[t]), 0.0f);
                __syncthreads();
                if (t < HID) {
                    float acc2[16];
#pragma unroll
                    for (int k = 0; k < 16; k++) acc2[k] = 0.0f;
                    for (int hp = 0; hp < HID; hp++) {
                        float wv = W2[hp * HID + t];
#pragma unroll
                        for (int k = 0; k < 16; k++)
                            acc2[k] = fmaf(h1s[k * HID + hp], wv, acc2[k]);
                    }
                    for (int k = 0; k < kk; k++)
                        if (i2 - (k0 + k + 1) >= 0)
                            hsum += fmaxf(acc2[k] + b2[t], 0.0f);
                }
            }
            if (t < HID) hsum_s[t] = hsum;
            __syncthreads();

            for (int j = t; j < NCO; j += 256) {
                float a = (float)nv2 * b3[j];
                for (int h = 0; h < HID; h++)
                    a = fmaf(hsum_s[h], W3[h * NCO + j], a);
                y2s[j] = a;
            }
            __syncthreads();
            if (t < COUT) {
                float a = 0.0f;
#pragma unroll
                for (int c = 0; c < CIN; c++) a = fmaf(fs2[c], y2s[c * COUT + t], a);
                out[(size_t)pos2 * COUT + t] = a;
            }
            __syncthreads();
        }
    }

    // ---- epilogue: last worker resets counters for the next replay ----
    __syncthreads();
    if (t == 0) {
        unsigned old = atomicAdd(&g_wdone, 1u);
        if (old == NWORKB - 1) {
            g_done  = 0u;
            g_wdone = 0u;
        }
    }
}

// ---------------------------------------------------------------------------
// kernel_launch: ONE graph node, allocation-free.
// Input order: times, features, W1, b1, W2, b2, W3, b3, kernel_size
// ---------------------------------------------------------------------------
extern "C" void kernel_launch(void* const* d_in, const int* in_sizes, int n_in,
                              void* d_out, int out_size) {
    const float* times = (const float*)d_in[0];
    const float* feat  = (const float*)d_in[1];
    const float* W1    = (const float*)d_in[2];
    const float* b1    = (const float*)d_in[3];
    const float* W2    = (const float*)d_in[4];
    const float* b2    = (const float*)d_in[5];
    const float* W3    = (const float*)d_in[6];
    const float* b3    = (const float*)d_in[7];
    const int*   Kp    = (n_in > 8) ? (const int*)d_in[8] : nullptr;
    float* out = (float*)d_out;

    fused_kernel<<<NBLK, 256>>>(times, feat, W1, b1, W2, b2, W3, b3, Kp, out);
}